// round 1
// baseline (speedup 1.0000x reference)
#include <cuda_runtime.h>
#include <math_constants.h>
#include <cfloat>

// Problem constants (B=2, L=256, A=12, C=32, K=30)
#define NB 2
#define NL 256
#define NA 12
#define NATOM 3072          // NL*NA
#define NC 32
#define KNB 30
#define BIGD 1000000.0f
#define MASKED_KEY 3.402823466e+38f  // FLT_MAX sentinel for masked candidates

// Output layout (all float32, concatenated in reference tuple order)
#define O_COORDS 0                       // (B, NATOM, 3)  -> 18432
#define O_MASK   (NB*NATOM*3)            // (B, NATOM)     -> 6144   @18432
#define O_ENC    (O_MASK + NB*NATOM)     // (B, NATOM, 32) -> 196608 @24576
#define O_DIST   (O_ENC + NB*NATOM*NC)   // (B, NATOM, 30) -> 184320 @221184
#define O_IDX    (O_DIST + NB*NATOM*KNB) // (B, NATOM, 30) -> 184320 @405504

__device__ float g_A[NB * NC];  // rstd * scale
__device__ float g_B[NB * NC];  // shift - mean * rstd * scale

// ---------------------------------------------------------------------------
// K0: per-(batch,channel) graph-norm stats (closed form).
// Each residue contributes every atom type exactly once, so
//   masked_sum[b,c] = nm[b] * colsum[c],  cnt = max(12*nm, 1)
//   var*cnt = nm * sum_a (T[a,c]-mean)^2 + (N - 12*nm) * mean^2
// ---------------------------------------------------------------------------
__global__ void stats_kernel(const int* __restrict__ mask,
                             const float* __restrict__ T,
                             const float* __restrict__ scale,
                             const float* __restrict__ shift) {
    int t = threadIdx.x;          // 64 threads: (b, c)
    int b = t >> 5;
    int c = t & 31;

    int nm = 0;
    #pragma unroll 8
    for (int l = 0; l < NL; ++l) nm += mask[b * NL + l];

    float colsum = 0.f;
    #pragma unroll
    for (int a = 0; a < NA; ++a) colsum += T[a * NC + c];

    float cntA = (float)(nm * NA);
    float cnt = fmaxf(cntA, 1.0f);
    float mean = ((float)nm * colsum) / cnt;

    float ssqm = 0.f;
    #pragma unroll
    for (int a = 0; a < NA; ++a) {
        float d = T[a * NC + c] - mean;
        ssqm = fmaf(d, d, ssqm);
    }
    float ssq = (float)nm * ssqm + ((float)NATOM - cntA) * mean * mean;
    float var = ssq / cnt;
    float rstd = 1.0f / sqrtf(var + 1e-5f);

    float Acoef = rstd * scale[c];
    g_A[t] = Acoef;
    g_B[t] = shift[c] - mean * Acoef;
}

// ---------------------------------------------------------------------------
// K1: write atom_coords (copy), atom_mask (repeat), encode (T*A + B, masked)
// ---------------------------------------------------------------------------
__global__ void write_kernel(const float* __restrict__ coords,
                             const int* __restrict__ mask,
                             const float* __restrict__ T,
                             float* __restrict__ out) {
    int tid = blockIdx.x * blockDim.x + threadIdx.x;   // 0 .. 196607

    if (tid < NB * NATOM * NC) {
        int b = tid / (NATOM * NC);
        int r = tid - b * NATOM * NC;
        int n = r >> 5;
        int c = r & 31;
        int m = mask[b * NL + n / NA];
        int ty = n % NA;
        float v = m ? fmaf(T[ty * NC + c], g_A[b * NC + c], g_B[b * NC + c]) : 0.0f;
        out[O_ENC + tid] = v;
    }
    if (tid < NB * NATOM * 3) {
        out[O_COORDS + tid] = coords[tid];
    }
    if (tid < NB * NATOM) {
        int b = tid / NATOM;
        int n = tid - b * NATOM;
        out[O_MASK + tid] = (float)mask[b * NL + n / NA];
    }
}

// ---------------------------------------------------------------------------
// K2: 30-NN per row. Warp-per-row, exact extract-min x30 with cooperative
// incremental rescan of only the invalidated lane's slice.
// smem: atoms as float4 (xyz + mask), d2 cache [32][97] per warp (pad->no conflicts)
// ---------------------------------------------------------------------------
#define ROWS_PER_BLOCK 8
#define TPAD 97
#define NT 96   // candidates per lane (3072/32)

__global__ void __launch_bounds__(256, 1)
knn_kernel(const float* __restrict__ coords,
           const int* __restrict__ mask,
           float* __restrict__ out) {
    extern __shared__ float smem[];
    float4* s_atoms = (float4*)smem;                 // NATOM float4 = 49152 B
    float*  s_d2    = smem + NATOM * 4;              // 8*32*97 floats = 99328 B

    int tid = threadIdx.x;
    int rowBase = blockIdx.x * ROWS_PER_BLOCK;
    int b = rowBase / NATOM;                          // block never straddles batches
    const float* cb = coords + b * NATOM * 3;
    const int* mb = mask + b * NL;

    // Cooperative load of this batch's atoms (+mask in .w)
    for (int a = tid; a < NATOM; a += 256) {
        float4 v;
        v.x = cb[a * 3 + 0];
        v.y = cb[a * 3 + 1];
        v.z = cb[a * 3 + 2];
        v.w = (float)mb[a / NA];
        s_atoms[a] = v;
    }
    __syncthreads();

    int warp = tid >> 5;
    int lane = tid & 31;
    int row = rowBase + warp;                 // global row (b * NATOM + ib)
    int ib = row - b * NATOM;

    float* dist_out = out + O_DIST + row * KNB;
    float* idx_out  = out + O_IDX  + row * KNB;

    float4 q = s_atoms[ib];
    if (q.w == 0.0f) {                        // masked row -> pad outputs
        if (lane < KNB) {
            dist_out[lane] = BIGD;
            idx_out[lane]  = 0.0f;
        }
        return;
    }

    float* my = s_d2 + warp * (32 * TPAD);

    // Phase A: compute d2 keys, cache in smem, track per-lane running min
    float bv = CUDART_INF_F;
    int   bj = 0x7fffffff;
    #pragma unroll 4
    for (int t = 0; t < NT; ++t) {
        int j = t * 32 + lane;
        float4 a = s_atoms[j];
        float dx = q.x - a.x, dy = q.y - a.y, dz = q.z - a.z;
        float d2 = fmaf(dx, dx, fmaf(dy, dy, dz * dz));
        float key = (a.w == 0.0f) ? MASKED_KEY : d2;
        my[lane * TPAD + t] = key;
        if (key < bv) { bv = key; bj = j; }   // within-lane: first (lowest j) wins ties
    }
    __syncwarp();

    float rv = 0.0f; int rj = 0;              // this lane's result slot (lane p holds pass p)
    for (int p = 0; p < KNB; ++p) {
        // global lexicographic (value, index) min via butterfly
        float mv = bv; int mj = bj;
        #pragma unroll
        for (int off = 16; off; off >>= 1) {
            float ov = __shfl_xor_sync(0xffffffffu, mv, off);
            int   oj = __shfl_xor_sync(0xffffffffu, mj, off);
            if (ov < mv || (ov == mv && oj < mj)) { mv = ov; mj = oj; }
        }
        if (lane == p) { rv = mv; rj = mj; }

        // invalidate extracted element; cooperatively rescan owner's slice
        int w  = mj & 31;
        int tm = mj >> 5;
        if (lane == w) my[w * TPAD + tm] = CUDART_INF_F;
        __syncwarp();

        if (p < KNB - 1) {
            float nv = CUDART_INF_F;
            int   nj = 0x7fffffff;
            #pragma unroll
            for (int s = 0; s < 3; ++s) {
                int t = lane + s * 32;
                float v = my[w * TPAD + t];
                int j = t * 32 + w;
                if (v < nv) { nv = v; nj = j; }   // t ascending -> lowest j on ties
            }
            #pragma unroll
            for (int off = 16; off; off >>= 1) {
                float ov = __shfl_xor_sync(0xffffffffu, nv, off);
                int   oj = __shfl_xor_sync(0xffffffffu, nj, off);
                if (ov < nv || (ov == nv && oj < nj)) { nv = ov; nj = oj; }
            }
            if (lane == w) { bv = nv; bj = nj; }
            __syncwarp();
        }
    }

    if (lane < KNB) {
        float dv = (rv == MASKED_KEY) ? BIGD : sqrtf(rv + 1e-6f);
        dist_out[lane] = dv;
        idx_out[lane]  = (float)rj;
    }
}

// ---------------------------------------------------------------------------
extern "C" void kernel_launch(void* const* d_in, const int* in_sizes, int n_in,
                              void* d_out, int out_size) {
    const float* coords = (const float*)d_in[0];   // (2,256,12,3) f32
    const int*   mask   = (const int*)d_in[1];     // (2,256) i32
    const float* emb    = (const float*)d_in[2];   // (12,32) f32
    const float* scale  = (const float*)d_in[3];   // (1,1,32) f32
    const float* shift  = (const float*)d_in[4];   // (1,1,32) f32
    float* out = (float*)d_out;

    stats_kernel<<<1, 64>>>(mask, emb, scale, shift);

    int enc_elems = NB * NATOM * NC;               // 196608
    write_kernel<<<(enc_elems + 255) / 256, 256>>>(coords, mask, emb, out);

    int smem_bytes = NATOM * 16 + ROWS_PER_BLOCK * 32 * TPAD * 4;   // 148480
    cudaFuncSetAttribute(knn_kernel, cudaFuncAttributeMaxDynamicSharedMemorySize,
                         smem_bytes);
    int nblocks = (NB * NATOM) / ROWS_PER_BLOCK;   // 768
    knn_kernel<<<nblocks, 256, smem_bytes>>>(coords, mask, out);
}

// round 2
// speedup vs baseline: 1.0035x; 1.0035x over previous
#include <cuda_runtime.h>
#include <math_constants.h>
#include <cfloat>

// Problem constants (B=2, L=256, A=12, C=32, K=30)
#define NB 2
#define NL 256
#define NA 12
#define NATOM 3072          // NL*NA
#define NC 32
#define KNB 30
#define BIGD 1000000.0f
#define MASKED_KEY 3.402823466e+38f  // FLT_MAX sentinel for masked candidates

// Output layout (all float32, concatenated in reference tuple order)
#define O_COORDS 0                       // (B, NATOM, 3)  -> 18432
#define O_MASK   (NB*NATOM*3)            // (B, NATOM)     -> 6144   @18432
#define O_ENC    (O_MASK + NB*NATOM)     // (B, NATOM, 32) -> 196608 @24576
#define O_DIST   (O_ENC + NB*NATOM*NC)   // (B, NATOM, 30) -> 184320 @221184
#define O_IDX    (O_DIST + NB*NATOM*KNB) // (B, NATOM, 30) -> 184320 @405504

__device__ float g_A[NB * NC];  // rstd * scale
__device__ float g_B[NB * NC];  // shift - mean * rstd * scale

// ---------------------------------------------------------------------------
// K0: per-(batch,channel) graph-norm stats (closed form).
// Each residue contributes every atom type exactly once, so
//   masked_sum[b,c] = nm[b] * colsum[c],  cnt = max(12*nm, 1)
//   var*cnt = nm * sum_a (T[a,c]-mean)^2 + (N - 12*nm) * mean^2
// ---------------------------------------------------------------------------
__global__ void stats_kernel(const int* __restrict__ mask,
                             const float* __restrict__ T,
                             const float* __restrict__ scale,
                             const float* __restrict__ shift) {
    int t = threadIdx.x;          // 64 threads: (b, c)
    int b = t >> 5;
    int c = t & 31;

    int nm = 0;
    #pragma unroll 8
    for (int l = 0; l < NL; ++l) nm += mask[b * NL + l];

    float colsum = 0.f;
    #pragma unroll
    for (int a = 0; a < NA; ++a) colsum += T[a * NC + c];

    float cntA = (float)(nm * NA);
    float cnt = fmaxf(cntA, 1.0f);
    float mean = ((float)nm * colsum) / cnt;

    float ssqm = 0.f;
    #pragma unroll
    for (int a = 0; a < NA; ++a) {
        float d = T[a * NC + c] - mean;
        ssqm = fmaf(d, d, ssqm);
    }
    float ssq = (float)nm * ssqm + ((float)NATOM - cntA) * mean * mean;
    float var = ssq / cnt;
    float rstd = 1.0f / sqrtf(var + 1e-5f);

    float Acoef = rstd * scale[c];
    g_A[t] = Acoef;
    g_B[t] = shift[c] - mean * Acoef;
}

// ---------------------------------------------------------------------------
// K1: write atom_coords (copy), atom_mask (repeat), encode (T*A + B, masked)
// ---------------------------------------------------------------------------
__global__ void write_kernel(const float* __restrict__ coords,
                             const int* __restrict__ mask,
                             const float* __restrict__ T,
                             float* __restrict__ out) {
    int tid = blockIdx.x * blockDim.x + threadIdx.x;   // 0 .. 196607

    if (tid < NB * NATOM * NC) {
        int b = tid / (NATOM * NC);
        int r = tid - b * NATOM * NC;
        int n = r >> 5;
        int c = r & 31;
        int m = mask[b * NL + n / NA];
        int ty = n % NA;
        float v = m ? fmaf(T[ty * NC + c], g_A[b * NC + c], g_B[b * NC + c]) : 0.0f;
        out[O_ENC + tid] = v;
    }
    if (tid < NB * NATOM * 3) {
        out[O_COORDS + tid] = coords[tid];
    }
    if (tid < NB * NATOM) {
        int b = tid / NATOM;
        int n = tid - b * NATOM;
        out[O_MASK + tid] = (float)mask[b * NL + n / NA];
    }
}

// ---------------------------------------------------------------------------
// K2: 30-NN per row. Warp-per-row, exact extract-min x30 with cooperative
// incremental rescan of only the invalidated lane's slice.
// smem: atoms as float4 (xyz + mask), d2 cache [32][97] per warp (pad->no conflicts)
// ---------------------------------------------------------------------------
#define ROWS_PER_BLOCK 8
#define TPAD 97
#define NT 96   // candidates per lane (3072/32)

__global__ void __launch_bounds__(256, 1)
knn_kernel(const float* __restrict__ coords,
           const int* __restrict__ mask,
           float* __restrict__ out) {
    extern __shared__ float smem[];
    float4* s_atoms = (float4*)smem;                 // NATOM float4 = 49152 B
    float*  s_d2    = smem + NATOM * 4;              // 8*32*97 floats = 99328 B

    int tid = threadIdx.x;
    int rowBase = blockIdx.x * ROWS_PER_BLOCK;
    int b = rowBase / NATOM;                          // block never straddles batches
    const float* cb = coords + b * NATOM * 3;
    const int* mb = mask + b * NL;

    // Cooperative load of this batch's atoms (+mask in .w)
    for (int a = tid; a < NATOM; a += 256) {
        float4 v;
        v.x = cb[a * 3 + 0];
        v.y = cb[a * 3 + 1];
        v.z = cb[a * 3 + 2];
        v.w = (float)mb[a / NA];
        s_atoms[a] = v;
    }
    __syncthreads();

    int warp = tid >> 5;
    int lane = tid & 31;
    int row = rowBase + warp;                 // global row (b * NATOM + ib)
    int ib = row - b * NATOM;

    float* dist_out = out + O_DIST + row * KNB;
    float* idx_out  = out + O_IDX  + row * KNB;

    float4 q = s_atoms[ib];
    if (q.w == 0.0f) {                        // masked row -> pad outputs
        if (lane < KNB) {
            dist_out[lane] = BIGD;
            idx_out[lane]  = 0.0f;
        }
        return;
    }

    float* my = s_d2 + warp * (32 * TPAD);

    // Phase A: compute d2 keys, cache in smem, track per-lane running min
    float bv = CUDART_INF_F;
    int   bj = 0x7fffffff;
    #pragma unroll 4
    for (int t = 0; t < NT; ++t) {
        int j = t * 32 + lane;
        float4 a = s_atoms[j];
        float dx = q.x - a.x, dy = q.y - a.y, dz = q.z - a.z;
        float d2 = fmaf(dx, dx, fmaf(dy, dy, dz * dz));
        float key = (a.w == 0.0f) ? MASKED_KEY : d2;
        my[lane * TPAD + t] = key;
        if (key < bv) { bv = key; bj = j; }   // within-lane: first (lowest j) wins ties
    }
    __syncwarp();

    float rv = 0.0f; int rj = 0;              // this lane's result slot (lane p holds pass p)
    for (int p = 0; p < KNB; ++p) {
        // global lexicographic (value, index) min via butterfly
        float mv = bv; int mj = bj;
        #pragma unroll
        for (int off = 16; off; off >>= 1) {
            float ov = __shfl_xor_sync(0xffffffffu, mv, off);
            int   oj = __shfl_xor_sync(0xffffffffu, mj, off);
            if (ov < mv || (ov == mv && oj < mj)) { mv = ov; mj = oj; }
        }
        if (lane == p) { rv = mv; rj = mj; }

        // invalidate extracted element; cooperatively rescan owner's slice
        int w  = mj & 31;
        int tm = mj >> 5;
        if (lane == w) my[w * TPAD + tm] = CUDART_INF_F;
        __syncwarp();

        if (p < KNB - 1) {
            float nv = CUDART_INF_F;
            int   nj = 0x7fffffff;
            #pragma unroll
            for (int s = 0; s < 3; ++s) {
                int t = lane + s * 32;
                float v = my[w * TPAD + t];
                int j = t * 32 + w;
                if (v < nv) { nv = v; nj = j; }   // t ascending -> lowest j on ties
            }
            #pragma unroll
            for (int off = 16; off; off >>= 1) {
                float ov = __shfl_xor_sync(0xffffffffu, nv, off);
                int   oj = __shfl_xor_sync(0xffffffffu, nj, off);
                if (ov < nv || (ov == nv && oj < nj)) { nv = ov; nj = oj; }
            }
            if (lane == w) { bv = nv; bj = nj; }
            __syncwarp();
        }
    }

    if (lane < KNB) {
        float dv = (rv == MASKED_KEY) ? BIGD : sqrtf(rv + 1e-6f);
        dist_out[lane] = dv;
        idx_out[lane]  = (float)rj;
    }
}

// ---------------------------------------------------------------------------
extern "C" void kernel_launch(void* const* d_in, const int* in_sizes, int n_in,
                              void* d_out, int out_size) {
    const float* coords = (const float*)d_in[0];   // (2,256,12,3) f32
    const int*   mask   = (const int*)d_in[1];     // (2,256) i32
    const float* emb    = (const float*)d_in[2];   // (12,32) f32
    const float* scale  = (const float*)d_in[3];   // (1,1,32) f32
    const float* shift  = (const float*)d_in[4];   // (1,1,32) f32
    float* out = (float*)d_out;

    stats_kernel<<<1, 64>>>(mask, emb, scale, shift);

    int enc_elems = NB * NATOM * NC;               // 196608
    write_kernel<<<(enc_elems + 255) / 256, 256>>>(coords, mask, emb, out);

    int smem_bytes = NATOM * 16 + ROWS_PER_BLOCK * 32 * TPAD * 4;   // 148480
    cudaFuncSetAttribute(knn_kernel, cudaFuncAttributeMaxDynamicSharedMemorySize,
                         smem_bytes);
    int nblocks = (NB * NATOM) / ROWS_PER_BLOCK;   // 768
    knn_kernel<<<nblocks, 256, smem_bytes>>>(coords, mask, out);
}

// round 3
// speedup vs baseline: 2.0585x; 2.0513x over previous
#include <cuda_runtime.h>
#include <math_constants.h>
#include <cfloat>

// Problem constants (B=2, L=256, A=12, C=32, K=30)
#define NB 2
#define NL 256
#define NA 12
#define NATOM 3072          // NL*NA
#define NC 32
#define KNB 30
#define BIGD 1000000.0f
#define MASKED_KEY 3.402823466e+38f  // FLT_MAX sentinel for masked candidates

// Output layout (all float32, concatenated in reference tuple order)
#define O_COORDS 0                       // (B, NATOM, 3)  -> 18432
#define O_MASK   (NB*NATOM*3)            // (B, NATOM)     -> 6144
#define O_ENC    (O_MASK + NB*NATOM)     // (B, NATOM, 32) -> 196608
#define O_DIST   (O_ENC + NB*NATOM*NC)   // (B, NATOM, 30) -> 184320
#define O_IDX    (O_DIST + NB*NATOM*KNB) // (B, NATOM, 30) -> 184320

#define ROWS 12              // rows (queries) per block
#define THREADS (ROWS * 32)  // 384
#define TPAD 97              // padded slice stride (32*97 floats per warp)
#define NT 96                // candidates per lane (3072/32)

__global__ void __launch_bounds__(THREADS, 1)
fused_kernel(const float* __restrict__ coords,
             const int* __restrict__ mask,
             const float* __restrict__ T,
             const float* __restrict__ scale,
             const float* __restrict__ shift,
             float* __restrict__ out) {
    extern __shared__ float smem[];
    float4* s_atoms = (float4*)smem;                 // NATOM float4 = 49152 B
    float*  s_d2    = smem + NATOM * 4;              // 12*32*97 floats = 148992 B
    __shared__ float s_red[8];

    int tid  = threadIdx.x;
    int warp = tid >> 5;
    int lane = tid & 31;

    int rowBase = blockIdx.x * ROWS;
    int b       = rowBase / NATOM;                   // blocks never straddle batches
    int ibBase  = rowBase - b * NATOM;
    const float* cb = coords + b * NATOM * 3;
    const int*   mb = mask + b * NL;

    // ---- cooperative load of this batch's atoms (xyz + mask in .w) ----
    for (int a = tid; a < NATOM; a += THREADS) {
        float4 v;
        v.x = cb[a * 3 + 0];
        v.y = cb[a * 3 + 1];
        v.z = cb[a * 3 + 2];
        v.w = (float)mb[a / NA];
        s_atoms[a] = v;
    }

    // ---- nm = sum(mask[b]) : warps 0..7 reduce 32 masks each ----
    if (tid < NL) {
        int v = mb[tid];
        int s = __reduce_add_sync(0xffffffffu, v);
        if (lane == 0) s_red[warp] = (float)s;
    }
    __syncthreads();

    float nm = 0.f;
    #pragma unroll
    for (int i = 0; i < 8; ++i) nm += s_red[i];

    // ---- per-(b,c) graph-norm affine coefficients (closed form) ----
    int c = lane;
    float tv[NA];
    float colsum = 0.f;
    #pragma unroll
    for (int a = 0; a < NA; ++a) { tv[a] = T[a * NC + c]; colsum += tv[a]; }

    float cntA = nm * (float)NA;
    float cnt  = fmaxf(cntA, 1.0f);
    float mean = (nm * colsum) / cnt;

    float ssqm = 0.f;
    #pragma unroll
    for (int a = 0; a < NA; ++a) {
        float d = tv[a] - mean;
        ssqm = fmaf(d, d, ssqm);
    }
    float ssq  = nm * ssqm + ((float)NATOM - cntA) * mean * mean;
    float rstd = rsqrtf(ssq / cnt + 1e-5f);
    float Ac   = rstd * scale[c];
    float Bc   = shift[c] - mean * Ac;

    // ---- small outputs: encode (one value per thread), coords copy, mask ----
    int row = rowBase + warp;
    int ib  = ibBase + warp;
    float4 q = s_atoms[ib];

    {
        int ty = ib % NA;
        float v = (q.w != 0.0f) ? fmaf(tv[ty], Ac, Bc) : 0.0f;
        out[O_ENC + row * NC + c] = v;
    }
    if (tid < ROWS * 3) out[O_COORDS + rowBase * 3 + tid] = coords[rowBase * 3 + tid];
    if (tid < ROWS)     out[O_MASK + rowBase + tid] = s_atoms[ibBase + tid].w;

    // ---- knn: warp-per-row extract-min x30 via redux.sync ----
    float* dist_out = out + O_DIST + row * KNB;
    float* idx_out  = out + O_IDX  + row * KNB;

    if (q.w == 0.0f) {                        // masked row -> pad outputs
        if (lane < KNB) {
            dist_out[lane] = BIGD;
            idx_out[lane]  = 0.0f;
        }
        return;
    }

    float* my = s_d2 + warp * (32 * TPAD);

    // Phase A: compute d2 keys, cache in smem, track per-lane running min (bits)
    unsigned bvb = 0xFFFFFFFFu;
    int bj = 0;
    #pragma unroll 4
    for (int t = 0; t < NT; ++t) {
        int j = t * 32 + lane;
        float4 a = s_atoms[j];
        float dx = q.x - a.x, dy = q.y - a.y, dz = q.z - a.z;
        float d2 = fmaf(dx, dx, fmaf(dy, dy, dz * dz));
        float key = (a.w == 0.0f) ? MASKED_KEY : d2;
        my[lane * TPAD + t] = key;
        unsigned kb = __float_as_uint(key);   // d2 >= 0 -> bits order-preserving
        if (kb < bvb) { bvb = kb; bj = j; }   // t ascending -> lowest j wins ties
    }
    __syncwarp();

    unsigned rvb = 0; int rj = 0;             // lane p holds pass-p result
    #pragma unroll 1
    for (int p = 0; p < KNB; ++p) {
        // global lexicographic (value, index) min via two redux
        unsigned mvb = __reduce_min_sync(0xffffffffu, bvb);
        unsigned cj  = (bvb == mvb) ? (unsigned)bj : 0xFFFFFFFFu;
        unsigned mj  = __reduce_min_sync(0xffffffffu, cj);
        if (lane == (unsigned)p) { rvb = mvb; rj = (int)mj; }

        if (p < KNB - 1) {
            int w  = (int)(mj & 31u);
            int tm = (int)(mj >> 5);
            // cooperative rescan of column w; owning lane self-excludes +
            // persists the invalidation for future rescans of this column
            unsigned nvb = 0xFFFFFFFFu;
            int nj = 0;
            #pragma unroll
            for (int s = 0; s < 3; ++s) {
                int t = lane + s * 32;
                float v = my[w * TPAD + t];
                unsigned vb2 = __float_as_uint(v);
                if (t == tm) { my[w * TPAD + t] = CUDART_INF_F; vb2 = 0xFFFFFFFFu; }
                if (vb2 < nvb) { nvb = vb2; nj = t * 32 + w; }
            }
            __syncwarp();                      // publish invalidation
            unsigned nmin = __reduce_min_sync(0xffffffffu, nvb);
            unsigned ncj  = (nvb == nmin) ? (unsigned)nj : 0xFFFFFFFFu;
            unsigned nidx = __reduce_min_sync(0xffffffffu, ncj);
            if (lane == w) { bvb = nmin; bj = (int)nidx; }
        }
    }

    if (lane < KNB) {
        float dv = (rvb == __float_as_uint(MASKED_KEY))
                       ? BIGD
                       : sqrtf(__uint_as_float(rvb) + 1e-6f);
        dist_out[lane] = dv;
        idx_out[lane]  = (float)rj;
    }
}

// ---------------------------------------------------------------------------
extern "C" void kernel_launch(void* const* d_in, const int* in_sizes, int n_in,
                              void* d_out, int out_size) {
    const float* coords = (const float*)d_in[0];   // (2,256,12,3) f32
    const int*   mask   = (const int*)d_in[1];     // (2,256) i32
    const float* emb    = (const float*)d_in[2];   // (12,32) f32
    const float* scale  = (const float*)d_in[3];   // (1,1,32) f32
    const float* shift  = (const float*)d_in[4];   // (1,1,32) f32
    float* out = (float*)d_out;

    int smem_bytes = NATOM * 16 + ROWS * 32 * TPAD * 4;   // 198144
    cudaFuncSetAttribute(fused_kernel, cudaFuncAttributeMaxDynamicSharedMemorySize,
                         smem_bytes);
    int nblocks = (NB * NATOM) / ROWS;   // 512
    fused_kernel<<<nblocks, THREADS, smem_bytes>>>(coords, mask, emb, scale, shift, out);
}